// round 16
// baseline (speedup 1.0000x reference)
#include <cuda_runtime.h>
#include <cuda_bf16.h>

#define NOUT 7
#define NS 14                      // OUT * RATIO sample points per axis
#define NCH 256
#define NBIN 49
#define ELEMS (NCH * NBIN)         // 12544 per ROI
#define CH_SPLIT 4                 // grid.y; channels per block = NCH / CH_SPLIT
#define CPB (NCH / CH_SPLIT)       // 64 channels per block
#define THREADS 224                // 14 iy * 16 ix-slots (14 active)

__global__ __launch_bounds__(THREADS, 7) void roi_pooler_kernel(
    const float* __restrict__ f0, const float* __restrict__ f1,
    const float* __restrict__ f2, const float* __restrict__ f3,
    const float* __restrict__ boxes, const int* __restrict__ bidx,
    float* __restrict__ out)
{
    const int roi = blockIdx.x;
    const int tid = threadIdx.x;

    __shared__ const float* sBase;   // feature base ptr incl. batch offset
    __shared__ int sHW;              // H*W (channel stride)
    __shared__ int sH, sW;
    __shared__ float sX0, sY0, sBw, sBh;
    __shared__ int   sYloW[NS], sYhiW[NS], sXlo[NS], sXhi[NS];
    __shared__ float sWyl[NS], sWyh[NS], sWxl[NS], sWxh[NS];

    if (tid == 0) {
        const float x0 = boxes[roi * 4 + 0];
        const float y0 = boxes[roi * 4 + 1];
        const float x1 = boxes[roi * 4 + 2];
        const float y1 = boxes[roi * 4 + 3];
        const float area = (x1 - x0) * (y1 - y0);
        const float size = sqrtf(area);
        // lvl = clip(floor(4 + log2(size/224 + 1e-8)), 2, 5) - 2
        float lf = floorf(4.0f + log2f(size / 224.0f + 1e-8f));
        lf = fminf(fmaxf(lf, 2.0f), 5.0f);
        const int lvl = (int)lf - 2;

        const float* fp; int H, W; float sc;
        switch (lvl) {
            case 0:  fp = f0; H = 200; W = 304; sc = 0.25f;    break;
            case 1:  fp = f1; H = 100; W = 152; sc = 0.125f;   break;
            case 2:  fp = f2; H =  50; W =  76; sc = 0.0625f;  break;
            default: fp = f3; H =  25; W =  38; sc = 0.03125f; break;
        }
        const int b = bidx[roi];
        sBase = fp + (size_t)b * NCH * H * W;
        sH = H; sW = W; sHW = H * W;
        sX0 = x0 * sc - 0.5f;
        sY0 = y0 * sc - 0.5f;
        sBw = (x1 - x0) * sc * (1.0f / NOUT);
        sBh = (y1 - y0) * sc * (1.0f / NOUT);
    }
    __syncthreads();

    // Axis weights: threads [0,14) handle x, [14,28) handle y.
    if (tid < 2 * NS) {
        const int  s   = (tid < NS) ? tid : tid - NS;
        const bool isY = (tid >= NS);
        const float off = (s + 0.5f) * 0.5f;   // s//2 + (s%2 + 0.5)/2
        const float c   = isY ? (sY0 + sBh * off) : (sX0 + sBw * off);
        const int   n   = isY ? sH : sW;
        const float fn  = (float)n;
        const float valid = (c >= -1.0f && c <= fn) ? 1.0f : 0.0f;
        const float cc    = fmaxf(c, 0.0f);
        const float lo_f  = floorf(cc);
        const bool  cap   = (lo_f >= fn - 1.0f);
        const int   lo    = cap ? (n - 1) : (int)lo_f;
        const int   hi    = cap ? (n - 1) : (lo + 1);
        const float l     = cap ? 0.0f : (cc - lo_f);
        const float wl    = (1.0f - l) * valid;
        const float wh    = l * valid;
        if (isY) {
            sYloW[s] = lo * sW; sYhiW[s] = hi * sW;
            sWyl[s] = wl;       sWyh[s] = wh;
        } else {
            sXlo[s] = lo;       sXhi[s] = hi;
            sWxl[s] = wl;       sWxh[s] = wh;
        }
    }
    __syncthreads();

    // Sample-point mapping: iy = tid>>4 (0..13), ix = tid&15 (active < 14,
    // pad lanes clamp to ix=13 and compute unused duplicates).
    // warp = tid>>5 = iy>>1 = ph; lane bit 4 = iy parity; lane bit 0 = ix parity.
    // Each thread computes one bilinear sample (4 taps); 2x2 sample->bin
    // reduction via shfl_xor(1) then shfl_xor(16). Writer lane per bin:
    // iy even, ix even, ix < 14; writes bin (ph = warp, pw = ix>>1).
    const int iy  = tid >> 4;
    const int ixr = tid & 15;
    const int ix  = (ixr < NS) ? ixr : (NS - 1);

    int   oLL, oLH, oHL, oHH;
    float wLL, wLH, wHL, wHH;
    {
        const int rlo = sYloW[iy], rhi = sYhiW[iy];
        const int clo = sXlo[ix],  chi = sXhi[ix];
        const float wyl = sWyl[iy] * 0.25f, wyh = sWyh[iy] * 0.25f;
        const float wxl = sWxl[ix],         wxh = sWxh[ix];
        oLL = rlo + clo;  wLL = wyl * wxl;
        oLH = rlo + chi;  wLH = wyl * wxh;
        oHL = rhi + clo;  wHL = wyh * wxl;
        oHH = rhi + chi;  wHH = wyh * wxh;
    }

    const bool writer = ((tid & 16) == 0) && ((ixr & 1) == 0) && (ixr < NS);

    const int HW = sHW;
    const int cb = blockIdx.y * CPB;   // this block's channel base
    // Strength-reduced pointers: advance by HW / NBIN per channel.
    const float* __restrict__ f = sBase + (size_t)cb * HW;
    float* __restrict__ outP = out + (size_t)roi * ELEMS + cb * NBIN
                             + (tid >> 5) * NOUT + (ixr >> 1);

    #pragma unroll 2
    for (int c = 0; c < CPB; c++) {
        float v = wLL * __ldg(f + oLL)
                + wLH * __ldg(f + oLH)
                + wHL * __ldg(f + oHL)
                + wHH * __ldg(f + oHH);
        v += __shfl_xor_sync(0xffffffffu, v, 1);    // combine x-sample pair
        v += __shfl_xor_sync(0xffffffffu, v, 16);   // combine y-sample pair
        if (writer) *outP = v;
        f    += HW;
        outP += NBIN;
    }
}

extern "C" void kernel_launch(void* const* d_in, const int* in_sizes, int n_in,
                              void* d_out, int out_size) {
    const float* f0    = (const float*)d_in[0];
    const float* f1    = (const float*)d_in[1];
    const float* f2    = (const float*)d_in[2];
    const float* f3    = (const float*)d_in[3];
    const float* boxes = (const float*)d_in[4];
    const int*   bidx  = (const int*)d_in[5];
    float*       out   = (float*)d_out;

    const int M = in_sizes[4] / 4;   // boxes is (M, 4)
    dim3 grid(M, CH_SPLIT);
    roi_pooler_kernel<<<grid, THREADS>>>(f0, f1, f2, f3, boxes, bidx, out);
}

// round 17
// speedup vs baseline: 1.6793x; 1.6793x over previous
#include <cuda_runtime.h>
#include <cuda_bf16.h>

#define NOUT 7
#define NS 14                      // OUT * RATIO sample points per axis
#define NCH 256
#define NBIN 49
#define ELEMS (NCH * NBIN)         // 12544 per ROI
#define CH_SPLIT 4                 // grid.y; channels per block = NCH / CH_SPLIT
#define CPB (NCH / CH_SPLIT)       // 64 channels per block
#define THREADS 224                // 14 iy * 16 ix-slots (14 active)

__global__ __launch_bounds__(THREADS, 6) void roi_pooler_kernel(
    const float* __restrict__ f0, const float* __restrict__ f1,
    const float* __restrict__ f2, const float* __restrict__ f3,
    const float* __restrict__ boxes, const int* __restrict__ bidx,
    float* __restrict__ out)
{
    const int roi = blockIdx.x;
    const int tid = threadIdx.x;

    __shared__ const float* sBase;   // feature base ptr incl. batch offset
    __shared__ int sHW;              // H*W (channel stride)
    __shared__ int sH, sW;
    __shared__ float sX0, sY0, sBw, sBh;
    __shared__ int   sYloW[NS], sYhiW[NS], sXlo[NS], sXhi[NS];
    __shared__ float sWyl[NS], sWyh[NS], sWxl[NS], sWxh[NS];

    if (tid == 0) {
        const float x0 = boxes[roi * 4 + 0];
        const float y0 = boxes[roi * 4 + 1];
        const float x1 = boxes[roi * 4 + 2];
        const float y1 = boxes[roi * 4 + 3];
        const float area = (x1 - x0) * (y1 - y0);
        const float size = sqrtf(area);
        // lvl = clip(floor(4 + log2(size/224 + 1e-8)), 2, 5) - 2
        float lf = floorf(4.0f + log2f(size / 224.0f + 1e-8f));
        lf = fminf(fmaxf(lf, 2.0f), 5.0f);
        const int lvl = (int)lf - 2;

        const float* fp; int H, W; float sc;
        switch (lvl) {
            case 0:  fp = f0; H = 200; W = 304; sc = 0.25f;    break;
            case 1:  fp = f1; H = 100; W = 152; sc = 0.125f;   break;
            case 2:  fp = f2; H =  50; W =  76; sc = 0.0625f;  break;
            default: fp = f3; H =  25; W =  38; sc = 0.03125f; break;
        }
        const int b = bidx[roi];
        sBase = fp + (size_t)b * NCH * H * W;
        sH = H; sW = W; sHW = H * W;
        sX0 = x0 * sc - 0.5f;
        sY0 = y0 * sc - 0.5f;
        sBw = (x1 - x0) * sc * (1.0f / NOUT);
        sBh = (y1 - y0) * sc * (1.0f / NOUT);
    }
    __syncthreads();

    // Axis weights: threads [0,14) handle x, [14,28) handle y.
    if (tid < 2 * NS) {
        const int  s   = (tid < NS) ? tid : tid - NS;
        const bool isY = (tid >= NS);
        const float off = (s + 0.5f) * 0.5f;   // s//2 + (s%2 + 0.5)/2
        const float c   = isY ? (sY0 + sBh * off) : (sX0 + sBw * off);
        const int   n   = isY ? sH : sW;
        const float fn  = (float)n;
        const float valid = (c >= -1.0f && c <= fn) ? 1.0f : 0.0f;
        const float cc    = fmaxf(c, 0.0f);
        const float lo_f  = floorf(cc);
        const bool  cap   = (lo_f >= fn - 1.0f);
        const int   lo    = cap ? (n - 1) : (int)lo_f;
        const int   hi    = cap ? (n - 1) : (lo + 1);
        const float l     = cap ? 0.0f : (cc - lo_f);
        const float wl    = (1.0f - l) * valid;
        const float wh    = l * valid;
        if (isY) {
            sYloW[s] = lo * sW; sYhiW[s] = hi * sW;
            sWyl[s] = wl;       sWyh[s] = wh;
        } else {
            sXlo[s] = lo;       sXhi[s] = hi;
            sWxl[s] = wl;       sWxh[s] = wh;
        }
    }
    __syncthreads();

    // Sample-point mapping: iy = tid>>4 (0..13), ix = tid&15 (active < 14,
    // pad lanes clamp to ix=13 and compute unused duplicates).
    // warp = tid>>5 = iy>>1 = ph; lane bit 4 = iy parity; lane bit 0 = ix parity.
    // Each thread computes one bilinear sample (4 taps) for TWO channels per
    // iteration; 2x2 sample->bin reduction via shfl_xor(1) then shfl_xor(16).
    const int iy  = tid >> 4;
    const int ixr = tid & 15;
    const int ix  = (ixr < NS) ? ixr : (NS - 1);

    int   oLL, oLH, oHL, oHH;
    float wLL, wLH, wHL, wHH;
    {
        const int rlo = sYloW[iy], rhi = sYhiW[iy];
        const int clo = sXlo[ix],  chi = sXhi[ix];
        const float wyl = sWyl[iy] * 0.25f, wyh = sWyh[iy] * 0.25f;
        const float wxl = sWxl[ix],         wxh = sWxh[ix];
        oLL = rlo + clo;  wLL = wyl * wxl;
        oLH = rlo + chi;  wLH = wyl * wxh;
        oHL = rhi + clo;  wHL = wyh * wxl;
        oHH = rhi + chi;  wHH = wyh * wxh;
    }

    const bool writer = ((tid & 16) == 0) && ((ixr & 1) == 0) && (ixr < NS);

    const int HW = sHW;
    const int cb = blockIdx.y * CPB;   // this block's channel base
    // Strength-reduced pointers; two channels per iteration share the taps.
    const float* __restrict__ f = sBase + (size_t)cb * HW;
    float* __restrict__ outP = out + (size_t)roi * ELEMS + cb * NBIN
                             + (tid >> 5) * NOUT + (ixr >> 1);

    #pragma unroll 1
    for (int c = 0; c < CPB; c += 2) {
        const float* __restrict__ fA = f;
        const float* __restrict__ fB = f + HW;
        float vA = wLL * __ldg(fA + oLL)
                 + wLH * __ldg(fA + oLH)
                 + wHL * __ldg(fA + oHL)
                 + wHH * __ldg(fA + oHH);
        float vB = wLL * __ldg(fB + oLL)
                 + wLH * __ldg(fB + oLH)
                 + wHL * __ldg(fB + oHL)
                 + wHH * __ldg(fB + oHH);
        vA += __shfl_xor_sync(0xffffffffu, vA, 1);    // x-sample pair
        vB += __shfl_xor_sync(0xffffffffu, vB, 1);
        vA += __shfl_xor_sync(0xffffffffu, vA, 16);   // y-sample pair
        vB += __shfl_xor_sync(0xffffffffu, vB, 16);
        if (writer) {
            outP[0]    = vA;
            outP[NBIN] = vB;
        }
        f    += 2 * HW;
        outP += 2 * NBIN;
    }
}

extern "C" void kernel_launch(void* const* d_in, const int* in_sizes, int n_in,
                              void* d_out, int out_size) {
    const float* f0    = (const float*)d_in[0];
    const float* f1    = (const float*)d_in[1];
    const float* f2    = (const float*)d_in[2];
    const float* f3    = (const float*)d_in[3];
    const float* boxes = (const float*)d_in[4];
    const int*   bidx  = (const int*)d_in[5];
    float*       out   = (float*)d_out;

    const int M = in_sizes[4] / 4;   // boxes is (M, 4)
    dim3 grid(M, CH_SPLIT);
    roi_pooler_kernel<<<grid, THREADS>>>(f0, f1, f2, f3, boxes, bidx, out);
}